// round 8
// baseline (speedup 1.0000x reference)
#include <cuda_runtime.h>
#include <cuda_fp16.h>
#include <cstdint>

#define NB_T 200
#define NB_NC 3
#define NGROUP 76800
#define NBOX   153600

// W2 transposed -> [N,K] row-major fp16
__device__ __half g_W2h[512 * 256];

__device__ __forceinline__ uint32_t smem_u32(const void* p){
    return (uint32_t)__cvta_generic_to_shared(p);
}

// Fast erf: Abramowitz-Stegun 7.1.26, |abs err| <= 1.5e-7
__device__ __forceinline__ float fast_erf(float x){
    float ax = fabsf(x);
    float t  = __frcp_rn(fmaf(0.3275911f, ax, 1.0f));
    float p  = fmaf(t, 1.061405429f, -1.453152027f);
    p = fmaf(t, p, 1.421413741f);
    p = fmaf(t, p, -0.284496736f);
    p = fmaf(t, p, 0.254829592f);
    p = p * t;
    float e  = __expf(-ax*ax);
    float r  = fmaf(-p, e, 1.0f);
    return copysignf(r, x);
}
__device__ __forceinline__ float gelu_fast(float x){
    return 0.5f * x * (1.0f + fast_erf(x * 0.70710678118654752440f));
}

#define CP16(dst, src) asm volatile("cp.async.cg.shared.global [%0], [%1], 16;\n" :: "r"(dst), "l"(src))
#define CPCOMMIT()     asm volatile("cp.async.commit_group;\n" ::: "memory")
#define CPWAIT1()      asm volatile("cp.async.wait_group 1;\n" ::: "memory")
#define CPWAIT0()      asm volatile("cp.async.wait_group 0;\n" ::: "memory")

__device__ __forceinline__ void ldsm_x4(uint32_t* r, uint32_t addr){
    asm volatile("ldmatrix.sync.aligned.m8n8.x4.shared.b16 {%0,%1,%2,%3}, [%4];\n"
        : "=r"(r[0]), "=r"(r[1]), "=r"(r[2]), "=r"(r[3]) : "r"(addr));
}
__device__ __forceinline__ void mma_f16(float* d, const uint32_t* a, const uint32_t* b){
    asm volatile(
        "mma.sync.aligned.m16n8k16.row.col.f32.f16.f16.f32 "
        "{%0,%1,%2,%3}, {%4,%5,%6,%7}, {%8,%9}, {%0,%1,%2,%3};\n"
        : "+f"(d[0]), "+f"(d[1]), "+f"(d[2]), "+f"(d[3])
        : "r"(a[0]), "r"(a[1]), "r"(a[2]), "r"(a[3]), "r"(b[0]), "r"(b[1]));
}

// ---------------------------------------------------------------------------
// k_w2: W2[K=256,N=512] row-major -> g_W2h[N,K] fp16
// ---------------------------------------------------------------------------
__global__ __launch_bounds__(256) void k_w2(const float* __restrict__ W2){
    int idx = blockIdx.x * 256 + threadIdx.x;   // 131072
    int k = idx >> 9, n = idx & 511;
    g_W2h[n * 256 + k] = __float2half(W2[idx]);
}

// ---------------------------------------------------------------------------
// Fused kernel: 1200 CTAs x 256 threads, 2 CTAs/SM.
// Phase 1: features for CTA's 64 groups -> A tile in SMEM (fp16, 264-half
//          row stride), meta -> SMEM, dist rows -> out.
// Phase 2: A resident; loop 4 N-tiles of 128: 2-stage cp.async B K-chunks,
//          fp16 mma m16n8k16 + ldmatrix, fused epilogue from SMEM tables.
// ---------------------------------------------------------------------------
#define ARST 264                 /* A row stride in halves (528 B) */
#define A_BYTES   (128*ARST*2)   /* 67584 */
#define BSTG_HALVES (128*40)     /* 5120 halves = 10240 B per stage */
#define B_OFF     A_BYTES
#define TAB_OFF   (B_OFF + 2*BSTG_HALVES*2)   /* 88064 */

__global__ __launch_bounds__(256, 2) void k_fused(
    const float* __restrict__ box,
    const float* __restrict__ W1, const float* __restrict__ b1,
    const float* __restrict__ lng, const float* __restrict__ lnb,
    const float* __restrict__ dist_w, const float* __restrict__ dist_b,
    const float* __restrict__ b2,
    const float* __restrict__ conf_w, const float* __restrict__ conf_b,
    const float* __restrict__ center_w, const float* __restrict__ center_b,
    const float* __restrict__ missing,
    const float* __restrict__ cat_table, const float* __restrict__ cam_table,
    const float* __restrict__ scalep,
    float* __restrict__ out)
{
    extern __shared__ __align__(16) char smraw[];
    __half* sA     = (__half*)smraw;
    float* s_cam3  = (float*)(smraw + TAB_OFF);     // 3*512 (b2+conf_b+center_b+cam)
    float* s_cat3  = s_cam3 + 3*512;                // 3*512
    float* s_cw    = s_cat3 + 3*512;                // 512
    float* s_c0    = s_cw + 512;
    float* s_c1    = s_c0 + 512;
    float* s_miss  = s_c1 + 512;
    float* s_mcat  = s_miss + 512;                  // 128 each
    float* s_mconf = s_mcat + 128;
    float* s_mcx   = s_mconf + 128;
    float* s_mcy   = s_mcx + 128;
    float* s_mpres = s_mcy + 128;

    const int tid  = threadIdx.x;
    const int lane = tid & 31;
    const int warp = tid >> 5;
    const int m0   = blockIdx.x * 128;

    // ---- epilogue tables (striped over all threads) ----
    for (int i = tid; i < 3*512; i += 256){
        int cc = i >> 9, d = i & 511;
        s_cam3[i] = b2[d] + conf_b[d] + center_b[d] + cam_table[cc*512 + d];
        s_cat3[i] = cat_table[cc*512 + d];
    }
    for (int d = tid; d < 512; d += 256){
        s_cw[d]   = conf_w[d];
        s_c0[d]   = center_w[d];
        s_c1[d]   = center_w[512 + d];
        s_miss[d] = missing[d];
    }

    // ================= Phase 1: features =================
    const float2* W1f2 = (const float2*)W1;
    const float2* b1f2 = (const float2*)b1;
    const float2* gf2  = (const float2*)lng;
    const float2* bbf2 = (const float2*)lnb;
    const float4* dw4  = (const float4*)dist_w;
    const float4* db4  = (const float4*)dist_b;

#pragma unroll 1
    for (int it = 0; it < 8; it++){
        const int g = blockIdx.x * 64 + warp * 8 + it;     // group index
        const int lrow0 = 2*(warp*8 + it);                 // local A rows

        const float4* bd4 = (const float4*)(box + (size_t)g * 12);
        float4 rA = __ldg(bd4), rB = __ldg(bd4+1), rC = __ldg(bd4+2);

        float c0[4], c1[4];
        c0[0]=rA.x/640.0f; c0[1]=rA.y/400.0f; c0[2]=rA.z/640.0f; c0[3]=rA.w/400.0f;
        c1[0]=rB.z/640.0f; c1[1]=rB.w/400.0f; c1[2]=rC.x/640.0f; c1[3]=rC.y/400.0f;
        float cat0=rB.x, conf0=rB.y, cat1=rC.z, conf1=rC.w;

        float s0 = ((c0[0]+c0[1])+c0[2])+c0[3];
        float s1 = ((c1[0]+c1[1])+c1[2])+c1[3];
        float p0 = (s0 != 0.0f) ? 1.0f : 0.0f;
        float p1 = (s1 != 0.0f) ? 1.0f : 0.0f;
        const bool swp = (cat1 + (1.0f-p1)*1000.0f) < (cat0 + (1.0f-p0)*1000.0f);

        float sc[2][4], scat[2], sconf[2], spres[2];
#pragma unroll
        for (int k = 0; k < 4; k++){
            sc[0][k] = swp ? c1[k] : c0[k];
            sc[1][k] = swp ? c0[k] : c1[k];
        }
        scat[0]=swp?cat1:cat0;   scat[1]=swp?cat0:cat1;
        sconf[0]=swp?conf1:conf0; sconf[1]=swp?conf0:conf1;
        spres[0]=swp?p1:p0;       spres[1]=swp?p0:p1;

        float feat[2][10], cxs[2], cys[2];
#pragma unroll
        for (int s = 0; s < 2; s++){
            float x1=sc[s][0], y1=sc[s][1], x2=sc[s][2], y2=sc[s][3];
            float w=x2-x1, h=y2-y1;
            float cx=(x1+x2)*0.5f, cy=(y1+y2)*0.5f;
            cxs[s]=cx; cys[s]=cy;
            feat[s][0]=x1; feat[s][1]=y1; feat[s][2]=x2; feat[s][3]=y2;
            feat[s][4]=w;  feat[s][5]=h;  feat[s][6]=cx; feat[s][7]=cy;
            feat[s][8]=w*h; feat[s][9]=w/(h+1e-6f);
        }

        float2 va[4], vb[4];
#pragma unroll
        for (int q = 0; q < 4; q++){
            int ci = lane + 32*q;
            float2 bias = __ldg(b1f2 + ci);
            float2 a0 = bias, a1 = bias;
#pragma unroll
            for (int f = 0; f < 10; f++){
                float2 w2 = __ldg(W1f2 + f*128 + ci);
                a0.x = fmaf(feat[0][f], w2.x, a0.x);
                a0.y = fmaf(feat[0][f], w2.y, a0.y);
                a1.x = fmaf(feat[1][f], w2.x, a1.x);
                a1.y = fmaf(feat[1][f], w2.y, a1.y);
            }
            va[q] = a0; vb[q] = a1;
        }

        float su0 = 0.f, su1 = 0.f;
#pragma unroll
        for (int q = 0; q < 4; q++){ su0 += va[q].x + va[q].y; su1 += vb[q].x + vb[q].y; }
#pragma unroll
        for (int o = 16; o; o >>= 1){
            su0 += __shfl_xor_sync(0xffffffffu, su0, o);
            su1 += __shfl_xor_sync(0xffffffffu, su1, o);
        }
        float mu0 = su0 * (1.0f/256.0f), mu1 = su1 * (1.0f/256.0f);

        float vr0 = 0.f, vr1 = 0.f;
#pragma unroll
        for (int q = 0; q < 4; q++){
            va[q].x -= mu0; va[q].y -= mu0;
            vb[q].x -= mu1; vb[q].y -= mu1;
            vr0 = fmaf(va[q].x, va[q].x, vr0); vr0 = fmaf(va[q].y, va[q].y, vr0);
            vr1 = fmaf(vb[q].x, vb[q].x, vr1); vr1 = fmaf(vb[q].y, vb[q].y, vr1);
        }
#pragma unroll
        for (int o = 16; o; o >>= 1){
            vr0 += __shfl_xor_sync(0xffffffffu, vr0, o);
            vr1 += __shfl_xor_sync(0xffffffffu, vr1, o);
        }
        float rs0 = rsqrtf(vr0 * (1.0f/256.0f) + 1e-5f);
        float rs1 = rsqrtf(vr1 * (1.0f/256.0f) + 1e-5f);

        __half2* hrow0 = (__half2*)(sA + lrow0*ARST);
        __half2* hrow1 = (__half2*)(sA + (lrow0+1)*ARST);
#pragma unroll
        for (int q = 0; q < 4; q++){
            int ci = lane + 32*q;
            float2 gb = __ldg(gf2 + ci), bv = __ldg(bbf2 + ci);
            float y00 = gelu_fast(va[q].x * rs0 * gb.x + bv.x);
            float y01 = gelu_fast(va[q].y * rs0 * gb.y + bv.y);
            float y10 = gelu_fast(vb[q].x * rs1 * gb.x + bv.x);
            float y11 = gelu_fast(vb[q].y * rs1 * gb.y + bv.y);
            hrow0[ci] = __floats2half2_rn(y00, y01);
            hrow1[ci] = __floats2half2_rn(y10, y11);
        }

        float dx = cxs[0]-cxs[1], dy = cys[0]-cys[1];
        float dist = sqrtf(dx*dx + dy*dy);
        const int bI = g / (NB_T*NB_NC);
        const int rem = g % (NB_T*NB_NC);
        float4* orow4 = (float4*)(out + ((size_t)bI * 1800 + rem) * 512);
#pragma unroll
        for (int jj = 0; jj < 4; jj++){
            int ci = lane + 32*jj;
            float4 w4 = __ldg(dw4 + ci), b4 = __ldg(db4 + ci);
            float4 r4;
            r4.x = fmaf(dist, w4.x, b4.x);
            r4.y = fmaf(dist, w4.y, b4.y);
            r4.z = fmaf(dist, w4.z, b4.z);
            r4.w = fmaf(dist, w4.w, b4.w);
            orow4[ci] = r4;
        }
        if (lane < 2){
            int lr = lrow0 + lane;
            s_mcat[lr]  = scat[lane];
            s_mconf[lr] = sconf[lane];
            s_mcx[lr]   = cxs[lane];
            s_mcy[lr]   = cys[lane];
            s_mpres[lr] = spres[lane];
        }
    }
    __syncthreads();

    // ================= Phase 2: GEMM =================
    const int wm  = warp & 1;      // 2 warps along M (64 rows each)
    const int wn  = warp >> 1;     // 4 warps along N (32 cols each)
    const int gid = lane >> 2;
    const int tig = lane & 3;

    const int a_row_sel = (lane & 7) + ((lane >> 3) & 1) * 8;
    const int a_col_sel = ((lane >> 4) & 1) * 8;
    const int b_row_sel = (lane & 7) + ((lane >> 4) & 1) * 8;
    const int b_col_sel = ((lane >> 3) & 1) * 8;

    const uint32_t sA32 = smem_u32(sA);
    const float scaleV = *scalep;

    auto load_B = [&](int stage, int nt, int kc){
        uint32_t base = smem_u32(smraw + B_OFF) + stage * (BSTG_HALVES*2);
#pragma unroll
        for (int u = 0; u < 2; u++){
            int c = tid + u*256;
            int n = c >> 2, seg = c & 3;
            const __half* src = g_W2h + (size_t)(nt*128 + n) * 256 + kc*32 + seg*8;
            CP16(base + n*80 + seg*16, src);
        }
    };

#pragma unroll 1
    for (int nt = 0; nt < 4; nt++){
        float acc[4][4][4];
#pragma unroll
        for (int i = 0; i < 4; i++)
#pragma unroll
            for (int j = 0; j < 4; j++)
#pragma unroll
                for (int k = 0; k < 4; k++) acc[i][j][k] = 0.0f;

        load_B(0, nt, 0); CPCOMMIT();

#pragma unroll 1
        for (int kc = 0; kc < 8; kc++){
            if (kc + 1 < 8){
                load_B((kc + 1) & 1, nt, kc + 1); CPCOMMIT();
                CPWAIT1();
            } else {
                CPWAIT0();
            }
            __syncthreads();

            const uint32_t b32 = smem_u32(smraw + B_OFF) + (kc & 1) * (BSTG_HALVES*2);

#pragma unroll
            for (int ks = 0; ks < 2; ks++){
                const int kk = kc*32 + ks*16;
                uint32_t af[4][4];
#pragma unroll
                for (int mi = 0; mi < 4; mi++){
                    int row = wm*64 + mi*16 + a_row_sel;
                    ldsm_x4(af[mi], sA32 + (row*ARST + kk + a_col_sel)*2);
                }
                uint32_t bf[4][2];
#pragma unroll
                for (int nio = 0; nio < 2; nio++){
                    uint32_t r[4];
                    int nrow = wn*32 + nio*16 + b_row_sel;
                    ldsm_x4(r, b32 + (nrow*40 + ks*16 + b_col_sel)*2);
                    bf[nio*2  ][0] = r[0]; bf[nio*2  ][1] = r[1];
                    bf[nio*2+1][0] = r[2]; bf[nio*2+1][1] = r[3];
                }
#pragma unroll
                for (int mi = 0; mi < 4; mi++)
#pragma unroll
                    for (int ni = 0; ni < 4; ni++)
                        mma_f16(acc[mi][ni], af[mi], bf[ni]);
            }
            __syncthreads();
        }

        // ---- epilogue for this n-tile ----
#pragma unroll
        for (int mi = 0; mi < 4; mi++){
#pragma unroll
            for (int h = 0; h < 2; h++){
                int lm = wm*64 + mi*16 + gid + h*8;
                int m  = m0 + lm;
                float cat = s_mcat[lm], conf = s_mconf[lm];
                float cxv = s_mcx[lm],  cyv  = s_mcy[lm];
                float pres = s_mpres[lm];
                int cam = (m >> 1) % 3;
                int icat = (int)cat;
                int bI  = m / 1200;
                int rem = m % 1200;
                float* orow = out + ((size_t)bI*1800 + 600 + rem) * 512 + nt*128;
                const float* camr = s_cam3 + cam*512 + nt*128;
                const float* catr = s_cat3 + icat*512 + nt*128;
                const float* cwr  = s_cw  + nt*128;
                const float* c0r  = s_c0  + nt*128;
                const float* c1r  = s_c1  + nt*128;
                const float* msr  = s_miss+ nt*128;
#pragma unroll
                for (int ni = 0; ni < 4; ni++){
                    int dl = wn*32 + ni*8 + tig*2;
                    float v0 = acc[mi][ni][h*2 + 0];
                    float v1 = acc[mi][ni][h*2 + 1];
                    v0 = (v0 + camr[dl]   + catr[dl]   + conf*cwr[dl]   + cxv*c0r[dl]   + cyv*c1r[dl])   * scaleV;
                    v1 = (v1 + camr[dl+1] + catr[dl+1] + conf*cwr[dl+1] + cxv*c0r[dl+1] + cyv*c1r[dl+1]) * scaleV;
                    if (pres == 0.0f){ v0 = msr[dl]; v1 = msr[dl+1]; }
                    float2 w2; w2.x = v0; w2.y = v1;
                    *reinterpret_cast<float2*>(orow + dl) = w2;
                }
            }
        }
    }
}

// ---------------------------------------------------------------------------
extern "C" void kernel_launch(void* const* d_in, const int* in_sizes, int n_in,
                              void* d_out, int out_size)
{
    const float* box        = (const float*)d_in[0];
    const float* cat_table  = (const float*)d_in[1];
    const float* W1         = (const float*)d_in[2];
    const float* b1         = (const float*)d_in[3];
    const float* lng        = (const float*)d_in[4];
    const float* lnb        = (const float*)d_in[5];
    const float* W2         = (const float*)d_in[6];
    const float* b2         = (const float*)d_in[7];
    const float* conf_w     = (const float*)d_in[8];
    const float* conf_b     = (const float*)d_in[9];
    const float* center_w   = (const float*)d_in[10];
    const float* center_b   = (const float*)d_in[11];
    const float* missing    = (const float*)d_in[12];
    const float* dist_w     = (const float*)d_in[13];
    const float* dist_b     = (const float*)d_in[14];
    const float* cam_table  = (const float*)d_in[15];
    const float* scalep     = (const float*)d_in[16];
    float* out = (float*)d_out;

    // dyn smem: A 67584 + B 20480 + tables 20480 + meta 2560 = 111104
    const int dyn_smem = 111104;
    cudaFuncSetAttribute(k_fused, cudaFuncAttributeMaxDynamicSharedMemorySize, dyn_smem);

    k_w2<<<512, 256>>>(W2);
    k_fused<<<1200, 256, dyn_smem>>>(box, W1, b1, lng, lnb, dist_w, dist_b,
                                     b2, conf_w, conf_b, center_w, center_b,
                                     missing, cat_table, cam_table, scalep, out);
}